// round 15
// baseline (speedup 1.0000x reference)
#include <cuda_runtime.h>
#include <math.h>

// Problem constants (validated against in_sizes at launch time)
#define NN 100000
#define NE 1600000
#define NF 64
#define NG 256

typedef unsigned long long ull;

// ---------------- device scratch (static; no allocations) ----------------
__device__ int    g_anyodd_v15;             // dtype probe: nonzero odd word seen
__device__ int    g_ecnt_v15;               // atomic base for fused scan
__device__ int    g_degi_v15[NN];           // degree incl. self loop
__device__ float  g_dinv_v15[NN];           // rsqrt(deg)
__device__ int    g_rp_v15[NN];             // CSR range start (disjoint partition)
__device__ int    g_pos_v15[NE];            // per-edge slot within dst's range
__device__ int    g_col_v15[NE];            // CSR column (src) indices
__device__ float4 g_bufA_v15[NN * 16];      // fp32 messages (row = 64 floats)
__device__ float4 g_bufB_v15[NN * 16];      // fp32 hidden state
__device__ float  g_sums_v15[NG * 64];      // pooled sums
__device__ int    g_cnt_v15[NG];            // nodes per graph

// dtype-agnostic index load: int64 buffers have zero odd (high) words.
__device__ __forceinline__ int ld_idx(const void* p, int i, int is64) {
    if (is64) return (int)((const long long*)p)[i];
    return ((const int*)p)[i];
}
__device__ __forceinline__ int clampi(int v, int hi) {
    return v < 0 ? 0 : (v > hi ? hi : v);
}

// packed fp32x2 FMA: acc.{lo,hi} += x * w.{lo,hi}
__device__ __forceinline__ void fma2(ull& acc, float x, ull w) {
    ull a;
    asm("mov.b64 %0, {%1, %1};" : "=l"(a) : "f"(x));
    asm("fma.rn.f32x2 %0, %1, %2, %3;" : "=l"(acc) : "l"(a), "l"(w), "l"(acc));
}

// ---------------- kernels ----------------

// init scratch + dtype probe (any nonzero odd 32-bit word => int32 data)
__global__ void initdet_v15(const int* ei_words, int n) {
    int i = blockIdx.x * blockDim.x + threadIdx.x;
    if (i == 0) { g_anyodd_v15 = 0; g_ecnt_v15 = 0; }
    if (i < n) g_degi_v15[i] = 1;            // self loop contributes 1
    if (i < NG * 64) g_sums_v15[i] = 0.0f;
    if (i < NG) g_cnt_v15[i] = 0;
    if (i < 2048 && ei_words[2 * i + 1] != 0) atomicOr(&g_anyodd_v15, 1);
}

// degree count; atomic return value doubles as the edge's slot index.
__global__ void count_v15(const void* ei, int E, int n) {
    int e = blockIdx.x * blockDim.x + threadIdx.x;
    if (e >= E) return;
    int is64 = (g_anyodd_v15 == 0);
    int d = clampi(ld_idx(ei, E + e, is64), n - 1);
    g_pos_v15[e] = atomicAdd(&g_degi_v15[d], 1) - 1;   // 0-based among real edges
}

// Fused single-pass "scan": block scans its chunk of (deg-1), grabs a global
// base via atomicAdd (ranges only need to be a disjoint partition of [0,E)).
__global__ void scanf_v15(int n) {
    __shared__ int wtot[17];
    __shared__ int base;
    int t = threadIdx.x;
    int i = blockIdx.x * 512 + t;
    int lane = t & 31;
    int w = t >> 5;

    if (t < 17) wtot[t] = 0;
    __syncthreads();

    int v = (i < n) ? (g_degi_v15[i] - 1) : 0;
    int s = v;
    #pragma unroll
    for (int off = 1; off < 32; off <<= 1) {
        int y = __shfl_up_sync(0xffffffffu, s, off);
        if (lane >= off) s += y;
    }
    if (lane == 31) wtot[w + 1] = s;
    __syncthreads();

    if (t == 0) {
        int acc = 0;
        #pragma unroll
        for (int k = 1; k <= 16; k++) { acc += wtot[k]; wtot[k] = acc; }
        base = atomicAdd(&g_ecnt_v15, acc);
    }
    __syncthreads();

    if (i < n) {
        g_rp_v15[i] = base + wtot[w] + (s - v);
        g_dinv_v15[i] = rsqrtf((float)g_degi_v15[i]);
    }
}

// atomic-free fill: slot was captured in count.
__global__ void fill_v15(const void* ei, int E, int n) {
    int e = blockIdx.x * blockDim.x + threadIdx.x;
    if (e >= E) return;
    int is64 = (g_anyodd_v15 == 0);
    int s = clampi(ld_idx(ei, e, is64), n - 1);
    int d = clampi(ld_idx(ei, E + e, is64), n - 1);
    g_col_v15[g_rp_v15[d] + g_pos_v15[e]] = s;
}

// bufA[i,:] = (X[i,:] @ W) * dinv[i].  X = input if use_ext else bufB.
// CTA = 256 threads = one 128-row tile (8 warps x 16 rows). X tile + W pairs
// staged in smem; packed f32x2 FMA. __launch_bounds__(256,3) -> 3 CTAs/SM.
__global__ void __launch_bounds__(256, 3) gemm_v15(const float* __restrict__ Xext,
                                                   int use_ext,
                                                   const float* __restrict__ W, int n) {
    __shared__ ulonglong2 Ws[32 * 32];   // 16KB: W pairs (paired-k layout)
    __shared__ float4 Xs[128 * 16];      // 32KB: X tile, row-major float4

    int tid = threadIdx.x;               // 0..255
    int lane = tid & 31;
    int wid = tid >> 5;                  // 0..7
    int tile = blockIdx.x;
    const float* X = use_ext ? Xext : (const float*)g_bufB_v15;

    // stage W: Ws[p*32+l] = { pair(W[2p][2l],W[2p][2l+1]), pair(W[2p+1][2l],W[2p+1][2l+1]) }
    for (int i = tid; i < 1024; i += 256) {
        int p = i >> 5, l = i & 31;
        ull a = ((const ull*)W)[(2 * p) * 32 + l];
        ull b = ((const ull*)W)[(2 * p + 1) * 32 + l];
        Ws[i] = make_ulonglong2(a, b);
    }

    // stage X tile: 2048 float4, 8 per thread, coalesced; clamp row for tail tile
    #pragma unroll
    for (int j = 0; j < 8; j++) {
        int i = j * 256 + tid;           // tile-local float4 index
        int r = i >> 4;                  // tile-local row
        int c = i & 15;                  // float4 column
        int row = tile * 128 + r; if (row > n - 1) row = n - 1;
        Xs[i] = ((const float4*)(X + (size_t)row * 64))[c];
    }
    __syncthreads();

    // compute: warp handles rows [wid*16, wid*16+16), 8 rows at a time
    #pragma unroll
    for (int g = 0; g < 2; g++) {
        int r0 = wid * 16 + g * 8;       // tile-local first row of the octet
        ull acc[8];
        #pragma unroll
        for (int r = 0; r < 8; r++) acc[r] = 0ull;

        #pragma unroll 4
        for (int q = 0; q < 16; q++) {
            ulonglong2 w0 = Ws[(2 * q) * 32 + lane];     // k = 4q, 4q+1
            ulonglong2 w1 = Ws[(2 * q + 1) * 32 + lane]; // k = 4q+2, 4q+3
            #pragma unroll
            for (int r = 0; r < 8; r++) {
                float4 xv = Xs[(r0 + r) * 16 + q];       // smem broadcast
                fma2(acc[r], xv.x, w0.x);
                fma2(acc[r], xv.y, w0.y);
                fma2(acc[r], xv.z, w1.x);
                fma2(acc[r], xv.w, w1.y);
            }
        }

        #pragma unroll
        for (int r = 0; r < 8; r++) {
            int row = tile * 128 + r0 + r;
            if (row < n) {
                float lo, hi;
                asm("mov.b64 {%0, %1}, %2;" : "=f"(lo), "=f"(hi) : "l"(acc[r]));
                float dv = g_dinv_v15[row];
                ((float2*)g_bufA_v15)[row * 32 + lane] = make_float2(lo * dv, hi * dv);
            }
        }
    }
}

// bufB[d,:] = relu( dinv[d] * (msg[d,:] + sum_{s in N(d)} msg[s,:]) + b )
// fp32 messages. Warp = node; lanes 0-15 even edges, 16-31 odd edges; each
// lane gathers one float4 chunk of the 256B row. Unroll-2 per half (4 edges
// in flight per warp). shfl.xor(16) combine.
__global__ void agg_v15(const float* __restrict__ bias, int n) {
    int node = (blockIdx.x * blockDim.x + threadIdx.x) >> 5;
    int lane = threadIdx.x & 31;
    if (node >= n) return;

    int half = lane >> 4;       // 0: even edges, 1: odd edges
    int c    = lane & 15;       // float4 chunk within row

    int beg = g_rp_v15[node];
    int end = beg + g_degi_v15[node] - 1;   // deg-1 real edges

    float4 acc, acc2 = make_float4(0.f, 0.f, 0.f, 0.f);
    if (half == 0) {
        acc = g_bufA_v15[node * 16 + c];     // self-loop term (pre-scaled)
    } else {
        acc = make_float4(0.f, 0.f, 0.f, 0.f);
    }

    int e = beg + half;
    for (; e + 2 < end; e += 4) {            // 2 edges of this half per iter
        int c0 = g_col_v15[e];
        int c1 = g_col_v15[e + 2];
        float4 v0 = g_bufA_v15[c0 * 16 + c];
        float4 v1 = g_bufA_v15[c1 * 16 + c];
        acc.x += v0.x;  acc.y += v0.y;  acc.z += v0.z;  acc.w += v0.w;
        acc2.x += v1.x; acc2.y += v1.y; acc2.z += v1.z; acc2.w += v1.w;
    }
    if (e < end) {
        int c0 = g_col_v15[e];
        float4 v0 = g_bufA_v15[c0 * 16 + c];
        acc.x += v0.x; acc.y += v0.y; acc.z += v0.z; acc.w += v0.w;
    }
    acc.x += acc2.x; acc.y += acc2.y; acc.z += acc2.z; acc.w += acc2.w;

    acc.x += __shfl_xor_sync(0xffffffffu, acc.x, 16);
    acc.y += __shfl_xor_sync(0xffffffffu, acc.y, 16);
    acc.z += __shfl_xor_sync(0xffffffffu, acc.z, 16);
    acc.w += __shfl_xor_sync(0xffffffffu, acc.w, 16);

    if (half == 0) {
        float dv = g_dinv_v15[node];
        float4 bb = ((const float4*)bias)[c];
        float4 o;
        o.x = fmaxf(fmaf(dv, acc.x, bb.x), 0.f);
        o.y = fmaxf(fmaf(dv, acc.y, bb.y), 0.f);
        o.z = fmaxf(fmaf(dv, acc.z, bb.z), 0.f);
        o.w = fmaxf(fmaf(dv, acc.w, bb.w), 0.f);
        g_bufB_v15[node * 16 + c] = o;
    }
}

// sorted-batch segment-sum with local run accumulation over bufB (fp32).
#define PNODES 512
__global__ void pool_v15(const void* batch, int n) {
    int base = blockIdx.x * PNODES;
    int l  = threadIdx.x & 31;            // float2 lane (features 2l, 2l+1)
    int rg = threadIdx.x >> 5;            // 0..7
    int is64 = (g_anyodd_v15 == 0);
    const float2* B2 = (const float2*)g_bufB_v15;
    float ax = 0.f, ay = 0.f;
    int cur = -1, cnt = 0;
    for (int i = rg; i < PNODES; i += 8) {
        int node = base + i;
        if (node >= n) break;
        int g = clampi(ld_idx(batch, node, is64), NG - 1);
        if (g != cur) {
            if (cur >= 0) {
                atomicAdd(&g_sums_v15[cur * 64 + 2 * l], ax);
                atomicAdd(&g_sums_v15[cur * 64 + 2 * l + 1], ay);
                if (l == 0) atomicAdd(&g_cnt_v15[cur], cnt);
            }
            cur = g; ax = 0.f; ay = 0.f; cnt = 0;
        }
        float2 v = B2[node * 32 + l];
        ax += v.x; ay += v.y;
        cnt++;
    }
    if (cur >= 0) {
        atomicAdd(&g_sums_v15[cur * 64 + 2 * l], ax);
        atomicAdd(&g_sums_v15[cur * 64 + 2 * l + 1], ay);
        if (l == 0) atomicAdd(&g_cnt_v15[cur], cnt);
    }
}

__global__ void head_v15(const float* __restrict__ Wfc,
                         const float* __restrict__ bfc,
                         float* __restrict__ out) {
    int g = blockIdx.x * blockDim.x + threadIdx.x;
    if (g >= NG) return;
    float acc = 0.f;
    #pragma unroll
    for (int j = 0; j < 64; j++)
        acc = fmaf(g_sums_v15[g * 64 + j], Wfc[j], acc);
    float c = (float)g_cnt_v15[g];
    if (c < 1.0f) c = 1.0f;
    float z = acc / c + bfc[0];
    out[g] = 1.0f / (1.0f + expf(-z));
}

// ---------------- launch (kernel launches only; graph-capturable) ----------------
extern "C" void kernel_launch(void* const* d_in, const int* in_sizes, int n_in,
                              void* d_out, int out_size) {
    const float* x     = (const float*)d_in[0];
    const void*  ei    = d_in[1];
    const void*  batch = d_in[2];
    const float* W1    = (const float*)d_in[3];
    const float* b1    = (const float*)d_in[4];
    const float* W2    = (const float*)d_in[5];
    const float* b2    = (const float*)d_in[6];
    const float* Wfc   = (const float*)d_in[7];
    const float* bfc   = (const float*)d_in[8];
    float* out = (float*)d_out;

    int N = in_sizes[0] / NF;              // 100000
    int E = in_sizes[1] / 2;               // 1600000
    if (N > NN) N = NN;
    if (E > NE) E = NE;

    int nScan  = (N + 511) / 512;
    int bEdge  = (E + 255) / 256;
    int bNode  = (N + 255) / 256;
    int bWarp  = (N + 7) / 8;              // agg: warp-per-node, 8 warps/block
    int nTiles = (N + 127) / 128;          // 782

    // Order: 4th launch (profiled slot) = gemm layer 1.
    initdet_v15<<<bNode, 256>>>((const int*)ei, N);        // 0
    count_v15<<<bEdge, 256>>>(ei, E, N);                   // 1
    scanf_v15<<<nScan, 512>>>(N);                          // 2
    gemm_v15<<<nTiles, 256>>>(x, 1, W1, N);                // 3  <-- profiled
    fill_v15<<<bEdge, 256>>>(ei, E, N);                    // 4
    agg_v15<<<bWarp, 256>>>(b1, N);                        // 5

    gemm_v15<<<nTiles, 256>>>(x, 0, W2, N);                // 6
    agg_v15<<<bWarp, 256>>>(b2, N);                        // 7

    pool_v15<<<(N + PNODES - 1) / PNODES, 256>>>(batch, N);// 8
    head_v15<<<1, 256>>>(Wfc, bfc, out);                   // 9
}

// round 16
// speedup vs baseline: 1.0809x; 1.0809x over previous
#include <cuda_runtime.h>
#include <math.h>

// Problem constants (validated against in_sizes at launch time)
#define NN 100000
#define NE 1600000
#define NF 64
#define NG 256

typedef unsigned long long ull;

// ---------------- device scratch (static; no allocations) ----------------
__device__ int    g_anyodd_v16;             // dtype probe: nonzero odd word seen
__device__ int    g_ecnt_v16;               // atomic base for fused scan
__device__ int    g_degi_v16[NN];           // degree incl. self loop
__device__ float  g_dinv_v16[NN];           // rsqrt(deg)
__device__ int    g_rp_v16[NN];             // CSR range start (disjoint partition)
__device__ int    g_pos_v16[NE];            // per-edge slot within dst's range
__device__ int    g_col_v16[NE];            // CSR column (src) indices
__device__ float4 g_bufA_v16[NN * 16];      // RAW messages X@W (row = 64 floats)
__device__ float4 g_bufB_v16[NN * 16];      // fp32 hidden state
__device__ float  g_sums_v16[NG * 64];      // pooled sums
__device__ int    g_cnt_v16[NG];            // nodes per graph

// dtype-agnostic index load: int64 buffers have zero odd (high) words.
__device__ __forceinline__ int ld_idx(const void* p, int i, int is64) {
    if (is64) return (int)((const long long*)p)[i];
    return ((const int*)p)[i];
}
__device__ __forceinline__ int clampi(int v, int hi) {
    return v < 0 ? 0 : (v > hi ? hi : v);
}

// packed fp32x2 FMA: acc.{lo,hi} += x * w.{lo,hi}
__device__ __forceinline__ void fma2(ull& acc, float x, ull w) {
    ull a;
    asm("mov.b64 %0, {%1, %1};" : "=l"(a) : "f"(x));
    asm("fma.rn.f32x2 %0, %1, %2, %3;" : "=l"(acc) : "l"(a), "l"(w), "l"(acc));
}

// ---------------- kernels ----------------

// init scratch + dtype probe (any nonzero odd 32-bit word => int32 data)
__global__ void initdet_v16(const int* ei_words, int n) {
    int i = blockIdx.x * blockDim.x + threadIdx.x;
    if (i == 0) { g_anyodd_v16 = 0; g_ecnt_v16 = 0; }
    if (i < n) g_degi_v16[i] = 1;            // self loop contributes 1
    if (i < NG * 64) g_sums_v16[i] = 0.0f;
    if (i < NG) g_cnt_v16[i] = 0;
    if (i < 2048 && ei_words[2 * i + 1] != 0) atomicOr(&g_anyodd_v16, 1);
}

// Hybrid kernel: blocks [0,nTiles) compute bufA = X@W (RAW, no dinv — so it is
// independent of the CSR build); blocks [nTiles, nTiles+ceil(E/256)) run the
// degree count. The two workloads overlap across SMs in one launch.
__global__ void __launch_bounds__(256, 3)
gemm_count_v16(const float* __restrict__ Xext, int use_ext,
               const float* __restrict__ W,
               const void* __restrict__ ei, int E, int n, int nTiles) {
    __shared__ ulonglong2 Ws[32 * 32];   // 16KB: W pairs (paired-k layout)
    __shared__ float4 Xs[128 * 16];      // 32KB: X tile, row-major float4

    int tid = threadIdx.x;               // 0..255

    if ((int)blockIdx.x >= nTiles) {     // ---- count path ----
        int e = ((int)blockIdx.x - nTiles) * 256 + tid;
        if (e < E) {
            int is64 = (g_anyodd_v16 == 0);
            int d = clampi(ld_idx(ei, E + e, is64), n - 1);
            g_pos_v16[e] = atomicAdd(&g_degi_v16[d], 1) - 1;
        }
        return;
    }

    // ---- gemm path ----
    int lane = tid & 31;
    int wid = tid >> 5;                  // 0..7
    int tile = blockIdx.x;
    const float* X = use_ext ? Xext : (const float*)g_bufB_v16;

    // stage W: Ws[p*32+l] = { pair(W[2p][2l],W[2p][2l+1]), pair(W[2p+1][2l],W[2p+1][2l+1]) }
    for (int i = tid; i < 1024; i += 256) {
        int p = i >> 5, l = i & 31;
        ull a = ((const ull*)W)[(2 * p) * 32 + l];
        ull b = ((const ull*)W)[(2 * p + 1) * 32 + l];
        Ws[i] = make_ulonglong2(a, b);
    }

    // stage X tile: 2048 float4, 8 per thread, coalesced; clamp row for tail tile
    #pragma unroll
    for (int j = 0; j < 8; j++) {
        int i = j * 256 + tid;           // tile-local float4 index
        int r = i >> 4;                  // tile-local row
        int c = i & 15;                  // float4 column
        int row = tile * 128 + r; if (row > n - 1) row = n - 1;
        Xs[i] = ((const float4*)(X + (size_t)row * 64))[c];
    }
    __syncthreads();

    // compute: warp handles rows [wid*16, wid*16+16), 8 rows at a time
    #pragma unroll
    for (int g = 0; g < 2; g++) {
        int r0 = wid * 16 + g * 8;
        ull acc[8];
        #pragma unroll
        for (int r = 0; r < 8; r++) acc[r] = 0ull;

        #pragma unroll 4
        for (int q = 0; q < 16; q++) {
            ulonglong2 w0 = Ws[(2 * q) * 32 + lane];     // k = 4q, 4q+1
            ulonglong2 w1 = Ws[(2 * q + 1) * 32 + lane]; // k = 4q+2, 4q+3
            #pragma unroll
            for (int r = 0; r < 8; r++) {
                float4 xv = Xs[(r0 + r) * 16 + q];       // smem broadcast
                fma2(acc[r], xv.x, w0.x);
                fma2(acc[r], xv.y, w0.y);
                fma2(acc[r], xv.z, w1.x);
                fma2(acc[r], xv.w, w1.y);
            }
        }

        #pragma unroll
        for (int r = 0; r < 8; r++) {
            int row = tile * 128 + r0 + r;
            if (row < n) {
                float lo, hi;
                asm("mov.b64 {%0, %1}, %2;" : "=f"(lo), "=f"(hi) : "l"(acc[r]));
                ((float2*)g_bufA_v16)[row * 32 + lane] = make_float2(lo, hi);
            }
        }
    }
}

// Fused single-pass "scan": block scans its chunk of (deg-1), grabs a global
// base via atomicAdd (ranges only need to be a disjoint partition of [0,E)).
__global__ void scanf_v16(int n) {
    __shared__ int wtot[17];
    __shared__ int base;
    int t = threadIdx.x;
    int i = blockIdx.x * 512 + t;
    int lane = t & 31;
    int w = t >> 5;

    if (t < 17) wtot[t] = 0;
    __syncthreads();

    int v = (i < n) ? (g_degi_v16[i] - 1) : 0;
    int s = v;
    #pragma unroll
    for (int off = 1; off < 32; off <<= 1) {
        int y = __shfl_up_sync(0xffffffffu, s, off);
        if (lane >= off) s += y;
    }
    if (lane == 31) wtot[w + 1] = s;
    __syncthreads();

    if (t == 0) {
        int acc = 0;
        #pragma unroll
        for (int k = 1; k <= 16; k++) { acc += wtot[k]; wtot[k] = acc; }
        base = atomicAdd(&g_ecnt_v16, acc);
    }
    __syncthreads();

    if (i < n) {
        g_rp_v16[i] = base + wtot[w] + (s - v);
        g_dinv_v16[i] = rsqrtf((float)g_degi_v16[i]);
    }
}

// atomic-free fill: slot was captured in count.
__global__ void fill_v16(const void* ei, int E, int n) {
    int e = blockIdx.x * blockDim.x + threadIdx.x;
    if (e >= E) return;
    int is64 = (g_anyodd_v16 == 0);
    int s = clampi(ld_idx(ei, e, is64), n - 1);
    int d = clampi(ld_idx(ei, E + e, is64), n - 1);
    g_col_v16[g_rp_v16[d] + g_pos_v16[e]] = s;
}

// bufB[d,:] = relu( dinv[d] * ( msg[d,:]*dinv[d] + sum_s msg[s,:]*dinv[s] ) + b )
// msg = RAW X@W rows; dinv applied per-gather (FFMA instead of FADD, free).
// Warp = node; lanes 0-15 even edges, 16-31 odd; lane gathers one float4
// chunk of the 256B row. shfl.xor(16) combine. (= v14 structure.)
__global__ void agg_v16(const float* __restrict__ bias, int n) {
    int node = (blockIdx.x * blockDim.x + threadIdx.x) >> 5;
    int lane = threadIdx.x & 31;
    if (node >= n) return;

    int half = lane >> 4;       // 0: even edges, 1: odd edges
    int c    = lane & 15;       // float4 chunk within row

    int beg = g_rp_v16[node];
    int end = beg + g_degi_v16[node] - 1;   // deg-1 real edges
    float dvn = g_dinv_v16[node];

    float4 acc;
    if (half == 0) {                         // self-loop term: msg[node]*dinv[node]
        float4 s = g_bufA_v16[node * 16 + c];
        acc = make_float4(s.x * dvn, s.y * dvn, s.z * dvn, s.w * dvn);
    } else {
        acc = make_float4(0.f, 0.f, 0.f, 0.f);
    }

    for (int e = beg + half; e < end; e += 2) {
        int col = g_col_v16[e];
        float dv = g_dinv_v16[col];
        float4 v = g_bufA_v16[col * 16 + c];
        acc.x = fmaf(v.x, dv, acc.x);
        acc.y = fmaf(v.y, dv, acc.y);
        acc.z = fmaf(v.z, dv, acc.z);
        acc.w = fmaf(v.w, dv, acc.w);
    }

    acc.x += __shfl_xor_sync(0xffffffffu, acc.x, 16);
    acc.y += __shfl_xor_sync(0xffffffffu, acc.y, 16);
    acc.z += __shfl_xor_sync(0xffffffffu, acc.z, 16);
    acc.w += __shfl_xor_sync(0xffffffffu, acc.w, 16);

    if (half == 0) {
        float4 bb = ((const float4*)bias)[c];
        float4 o;
        o.x = fmaxf(fmaf(dvn, acc.x, bb.x), 0.f);
        o.y = fmaxf(fmaf(dvn, acc.y, bb.y), 0.f);
        o.z = fmaxf(fmaf(dvn, acc.z, bb.z), 0.f);
        o.w = fmaxf(fmaf(dvn, acc.w, bb.w), 0.f);
        g_bufB_v16[node * 16 + c] = o;
    }
}

// sorted-batch segment-sum with local run accumulation over bufB (fp32).
#define PNODES 512
__global__ void pool_v16(const void* batch, int n) {
    int base = blockIdx.x * PNODES;
    int l  = threadIdx.x & 31;            // float2 lane (features 2l, 2l+1)
    int rg = threadIdx.x >> 5;            // 0..7
    int is64 = (g_anyodd_v16 == 0);
    const float2* B2 = (const float2*)g_bufB_v16;
    float ax = 0.f, ay = 0.f;
    int cur = -1, cnt = 0;
    for (int i = rg; i < PNODES; i += 8) {
        int node = base + i;
        if (node >= n) break;
        int g = clampi(ld_idx(batch, node, is64), NG - 1);
        if (g != cur) {
            if (cur >= 0) {
                atomicAdd(&g_sums_v16[cur * 64 + 2 * l], ax);
                atomicAdd(&g_sums_v16[cur * 64 + 2 * l + 1], ay);
                if (l == 0) atomicAdd(&g_cnt_v16[cur], cnt);
            }
            cur = g; ax = 0.f; ay = 0.f; cnt = 0;
        }
        float2 v = B2[node * 32 + l];
        ax += v.x; ay += v.y;
        cnt++;
    }
    if (cur >= 0) {
        atomicAdd(&g_sums_v16[cur * 64 + 2 * l], ax);
        atomicAdd(&g_sums_v16[cur * 64 + 2 * l + 1], ay);
        if (l == 0) atomicAdd(&g_cnt_v16[cur], cnt);
    }
}

__global__ void head_v16(const float* __restrict__ Wfc,
                         const float* __restrict__ bfc,
                         float* __restrict__ out) {
    int g = blockIdx.x * blockDim.x + threadIdx.x;
    if (g >= NG) return;
    float acc = 0.f;
    #pragma unroll
    for (int j = 0; j < 64; j++)
        acc = fmaf(g_sums_v16[g * 64 + j], Wfc[j], acc);
    float c = (float)g_cnt_v16[g];
    if (c < 1.0f) c = 1.0f;
    float z = acc / c + bfc[0];
    out[g] = 1.0f / (1.0f + expf(-z));
}

// ---------------- launch (kernel launches only; graph-capturable) ----------------
extern "C" void kernel_launch(void* const* d_in, const int* in_sizes, int n_in,
                              void* d_out, int out_size) {
    const float* x     = (const float*)d_in[0];
    const void*  ei    = d_in[1];
    const void*  batch = d_in[2];
    const float* W1    = (const float*)d_in[3];
    const float* b1    = (const float*)d_in[4];
    const float* W2    = (const float*)d_in[5];
    const float* b2    = (const float*)d_in[6];
    const float* Wfc   = (const float*)d_in[7];
    const float* bfc   = (const float*)d_in[8];
    float* out = (float*)d_out;

    int N = in_sizes[0] / NF;              // 100000
    int E = in_sizes[1] / 2;               // 1600000
    if (N > NN) N = NN;
    if (E > NE) E = NE;

    int nScan  = (N + 511) / 512;
    int bEdge  = (E + 255) / 256;          // 6250
    int bNode  = (N + 255) / 256;
    int bWarp  = (N + 7) / 8;              // agg: warp-per-node, 8 warps/block
    int nTiles = (N + 127) / 128;          // 782

    initdet_v16<<<bNode, 256>>>((const int*)ei, N);                    // 0
    // gemm1 (CSR-independent, raw X@W) overlapped with degree count:
    gemm_count_v16<<<nTiles + bEdge, 256>>>(x, 1, W1, ei, E, N, nTiles); // 1
    scanf_v16<<<nScan, 512>>>(N);                                      // 2
    fill_v16<<<bEdge, 256>>>(ei, E, N);                                // 3  <-- profiled
    agg_v16<<<bWarp, 256>>>(b1, N);                                    // 4

    // layer 2 (no count blocks)
    gemm_count_v16<<<nTiles, 256>>>(x, 0, W2, ei, E, N, nTiles);       // 5
    agg_v16<<<bWarp, 256>>>(b2, N);                                    // 6

    pool_v16<<<(N + PNODES - 1) / PNODES, 256>>>(batch, N);            // 7
    head_v16<<<1, 256>>>(Wfc, bfc, out);                               // 8
}

// round 17
// speedup vs baseline: 1.1375x; 1.0524x over previous
#include <cuda_runtime.h>
#include <math.h>

// Problem constants (validated against in_sizes at launch time)
#define NN 100000
#define NE 1600000
#define NF 64
#define NG 256

typedef unsigned long long ull;

// ---------------- device scratch (static; no allocations) ----------------
__device__ int    g_anyodd_v17;             // dtype probe: nonzero odd word seen
__device__ int    g_ecnt_v17;               // atomic base for fused scan
__device__ int    g_degi_v17[NN];           // degree incl. self loop
__device__ float  g_dinv_v17[NN];           // rsqrt(deg)
__device__ int    g_rp_v17[NN];             // CSR range start (disjoint partition)
__device__ int    g_pos_v17[NE];            // per-edge slot within dst's range
__device__ int    g_col_v17[NE];            // CSR column (src) indices
__device__ float4 g_bufA_v17[NN * 16];      // messages (X@W)*dinv (row = 64 floats)
__device__ float4 g_bufB_v17[NN * 16];      // fp32 hidden state
__device__ float  g_sums_v17[NG * 64];      // pooled sums
__device__ int    g_cnt_v17[NG];            // nodes per graph

// dtype-agnostic index load: int64 buffers have zero odd (high) words.
__device__ __forceinline__ int ld_idx(const void* p, int i, int is64) {
    if (is64) return (int)((const long long*)p)[i];
    return ((const int*)p)[i];
}
__device__ __forceinline__ int clampi(int v, int hi) {
    return v < 0 ? 0 : (v > hi ? hi : v);
}

// packed fp32x2 FMA: acc.{lo,hi} += x * w.{lo,hi}
__device__ __forceinline__ void fma2(ull& acc, float x, ull w) {
    ull a;
    asm("mov.b64 %0, {%1, %1};" : "=l"(a) : "f"(x));
    asm("fma.rn.f32x2 %0, %1, %2, %3;" : "=l"(acc) : "l"(a), "l"(w), "l"(acc));
}

// ---------------- kernels ----------------

// init scratch + dtype probe (any nonzero odd 32-bit word => int32 data)
__global__ void initdet_v17(const int* ei_words, int n) {
    int i = blockIdx.x * blockDim.x + threadIdx.x;
    if (i == 0) { g_anyodd_v17 = 0; g_ecnt_v17 = 0; }
    if (i < n) g_degi_v17[i] = 1;            // self loop contributes 1
    if (i < NG * 64) g_sums_v17[i] = 0.0f;
    if (i < NG) g_cnt_v17[i] = 0;
    if (i < 2048 && ei_words[2 * i + 1] != 0) atomicOr(&g_anyodd_v17, 1);
}

// degree count; atomic return value doubles as the edge's slot index.
__global__ void count_v17(const void* ei, int E, int n) {
    int e = blockIdx.x * blockDim.x + threadIdx.x;
    if (e >= E) return;
    int is64 = (g_anyodd_v17 == 0);
    int d = clampi(ld_idx(ei, E + e, is64), n - 1);
    g_pos_v17[e] = atomicAdd(&g_degi_v17[d], 1) - 1;   // 0-based among real edges
}

// Fused single-pass "scan": block scans its chunk of (deg-1), grabs a global
// base via atomicAdd (ranges only need to be a disjoint partition of [0,E)).
__global__ void scanf_v17(int n) {
    __shared__ int wtot[17];
    __shared__ int base;
    int t = threadIdx.x;
    int i = blockIdx.x * 512 + t;
    int lane = t & 31;
    int w = t >> 5;

    if (t < 17) wtot[t] = 0;
    __syncthreads();

    int v = (i < n) ? (g_degi_v17[i] - 1) : 0;
    int s = v;
    #pragma unroll
    for (int off = 1; off < 32; off <<= 1) {
        int y = __shfl_up_sync(0xffffffffu, s, off);
        if (lane >= off) s += y;
    }
    if (lane == 31) wtot[w + 1] = s;
    __syncthreads();

    if (t == 0) {
        int acc = 0;
        #pragma unroll
        for (int k = 1; k <= 16; k++) { acc += wtot[k]; wtot[k] = acc; }
        base = atomicAdd(&g_ecnt_v17, acc);
    }
    __syncthreads();

    if (i < n) {
        g_rp_v17[i] = base + wtot[w] + (s - v);
        g_dinv_v17[i] = rsqrtf((float)g_degi_v17[i]);
    }
}

// Hybrid: blocks [0,nTiles) run the GEMM (with dinv epilogue); blocks
// [nTiles, nTiles+ceil(E/256)) run the atomic-free CSR fill. Both depend only
// on scanf's outputs and stress disjoint pipes (fma/LDS vs L2 scatter), so
// they overlap across SMs in one launch.
__global__ void __launch_bounds__(256, 3)
gemm_fill_v17(const float* __restrict__ Xext, int use_ext,
              const float* __restrict__ W,
              const void* __restrict__ ei, int E, int n, int nTiles) {
    __shared__ ulonglong2 Ws[32 * 32];   // 16KB: W pairs (paired-k layout)
    __shared__ float4 Xs[128 * 16];      // 32KB: X tile, row-major float4

    int tid = threadIdx.x;               // 0..255

    if ((int)blockIdx.x >= nTiles) {     // ---- fill path ----
        int e = ((int)blockIdx.x - nTiles) * 256 + tid;
        if (e < E) {
            int is64 = (g_anyodd_v17 == 0);
            int s = clampi(ld_idx(ei, e, is64), n - 1);
            int d = clampi(ld_idx(ei, E + e, is64), n - 1);
            g_col_v17[g_rp_v17[d] + g_pos_v17[e]] = s;
        }
        return;
    }

    // ---- gemm path: bufA[i,:] = (X[i,:] @ W) * dinv[i] ----
    int lane = tid & 31;
    int wid = tid >> 5;                  // 0..7
    int tile = blockIdx.x;
    const float* X = use_ext ? Xext : (const float*)g_bufB_v17;

    // stage W: Ws[p*32+l] = { pair(W[2p][2l],W[2p][2l+1]), pair(W[2p+1][2l],W[2p+1][2l+1]) }
    for (int i = tid; i < 1024; i += 256) {
        int p = i >> 5, l = i & 31;
        ull a = ((const ull*)W)[(2 * p) * 32 + l];
        ull b = ((const ull*)W)[(2 * p + 1) * 32 + l];
        Ws[i] = make_ulonglong2(a, b);
    }

    // stage X tile: 2048 float4, 8 per thread, coalesced; clamp row for tail tile
    #pragma unroll
    for (int j = 0; j < 8; j++) {
        int i = j * 256 + tid;           // tile-local float4 index
        int r = i >> 4;                  // tile-local row
        int c = i & 15;                  // float4 column
        int row = tile * 128 + r; if (row > n - 1) row = n - 1;
        Xs[i] = ((const float4*)(X + (size_t)row * 64))[c];
    }
    __syncthreads();

    // compute: warp handles rows [wid*16, wid*16+16), 8 rows at a time
    #pragma unroll
    for (int g = 0; g < 2; g++) {
        int r0 = wid * 16 + g * 8;
        ull acc[8];
        #pragma unroll
        for (int r = 0; r < 8; r++) acc[r] = 0ull;

        #pragma unroll 4
        for (int q = 0; q < 16; q++) {
            ulonglong2 w0 = Ws[(2 * q) * 32 + lane];     // k = 4q, 4q+1
            ulonglong2 w1 = Ws[(2 * q + 1) * 32 + lane]; // k = 4q+2, 4q+3
            #pragma unroll
            for (int r = 0; r < 8; r++) {
                float4 xv = Xs[(r0 + r) * 16 + q];       // smem broadcast
                fma2(acc[r], xv.x, w0.x);
                fma2(acc[r], xv.y, w0.y);
                fma2(acc[r], xv.z, w1.x);
                fma2(acc[r], xv.w, w1.y);
            }
        }

        #pragma unroll
        for (int r = 0; r < 8; r++) {
            int row = tile * 128 + r0 + r;
            if (row < n) {
                float lo, hi;
                asm("mov.b64 {%0, %1}, %2;" : "=f"(lo), "=f"(hi) : "l"(acc[r]));
                float dv = g_dinv_v17[row];
                ((float2*)g_bufA_v17)[row * 32 + lane] = make_float2(lo * dv, hi * dv);
            }
        }
    }
}

// bufB[d,:] = relu( dinv[d] * (msg[d,:] + sum_{s in N(d)} msg[s,:]) + b )
// msg rows pre-scaled by dinv[src] (gemm epilogue). Warp = node; lanes 0-15
// even edges, 16-31 odd; lane gathers one float4 chunk of the 256B row.
// shfl.xor(16) combine. (= proven v14 structure.)
__global__ void agg_v17(const float* __restrict__ bias, int n) {
    int node = (blockIdx.x * blockDim.x + threadIdx.x) >> 5;
    int lane = threadIdx.x & 31;
    if (node >= n) return;

    int half = lane >> 4;       // 0: even edges, 1: odd edges
    int c    = lane & 15;       // float4 chunk within row

    int beg = g_rp_v17[node];
    int end = beg + g_degi_v17[node] - 1;   // deg-1 real edges

    float4 acc;
    if (half == 0) {
        acc = g_bufA_v17[node * 16 + c];     // self-loop term (pre-scaled)
    } else {
        acc = make_float4(0.f, 0.f, 0.f, 0.f);
    }

    for (int e = beg + half; e < end; e += 2) {
        int col = g_col_v17[e];
        float4 v = g_bufA_v17[col * 16 + c];
        acc.x += v.x; acc.y += v.y; acc.z += v.z; acc.w += v.w;
    }

    acc.x += __shfl_xor_sync(0xffffffffu, acc.x, 16);
    acc.y += __shfl_xor_sync(0xffffffffu, acc.y, 16);
    acc.z += __shfl_xor_sync(0xffffffffu, acc.z, 16);
    acc.w += __shfl_xor_sync(0xffffffffu, acc.w, 16);

    if (half == 0) {
        float dv = g_dinv_v17[node];
        float4 bb = ((const float4*)bias)[c];
        float4 o;
        o.x = fmaxf(fmaf(dv, acc.x, bb.x), 0.f);
        o.y = fmaxf(fmaf(dv, acc.y, bb.y), 0.f);
        o.z = fmaxf(fmaf(dv, acc.z, bb.z), 0.f);
        o.w = fmaxf(fmaf(dv, acc.w, bb.w), 0.f);
        g_bufB_v17[node * 16 + c] = o;
    }
}

// sorted-batch segment-sum with local run accumulation over bufB (fp32).
#define PNODES 512
__global__ void pool_v17(const void* batch, int n) {
    int base = blockIdx.x * PNODES;
    int l  = threadIdx.x & 31;            // float2 lane (features 2l, 2l+1)
    int rg = threadIdx.x >> 5;            // 0..7
    int is64 = (g_anyodd_v17 == 0);
    const float2* B2 = (const float2*)g_bufB_v17;
    float ax = 0.f, ay = 0.f;
    int cur = -1, cnt = 0;
    for (int i = rg; i < PNODES; i += 8) {
        int node = base + i;
        if (node >= n) break;
        int g = clampi(ld_idx(batch, node, is64), NG - 1);
        if (g != cur) {
            if (cur >= 0) {
                atomicAdd(&g_sums_v17[cur * 64 + 2 * l], ax);
                atomicAdd(&g_sums_v17[cur * 64 + 2 * l + 1], ay);
                if (l == 0) atomicAdd(&g_cnt_v17[cur], cnt);
            }
            cur = g; ax = 0.f; ay = 0.f; cnt = 0;
        }
        float2 v = B2[node * 32 + l];
        ax += v.x; ay += v.y;
        cnt++;
    }
    if (cur >= 0) {
        atomicAdd(&g_sums_v17[cur * 64 + 2 * l], ax);
        atomicAdd(&g_sums_v17[cur * 64 + 2 * l + 1], ay);
        if (l == 0) atomicAdd(&g_cnt_v17[cur], cnt);
    }
}

__global__ void head_v17(const float* __restrict__ Wfc,
                         const float* __restrict__ bfc,
                         float* __restrict__ out) {
    int g = blockIdx.x * blockDim.x + threadIdx.x;
    if (g >= NG) return;
    float acc = 0.f;
    #pragma unroll
    for (int j = 0; j < 64; j++)
        acc = fmaf(g_sums_v17[g * 64 + j], Wfc[j], acc);
    float c = (float)g_cnt_v17[g];
    if (c < 1.0f) c = 1.0f;
    float z = acc / c + bfc[0];
    out[g] = 1.0f / (1.0f + expf(-z));
}

// ---------------- launch (kernel launches only; graph-capturable) ----------------
extern "C" void kernel_launch(void* const* d_in, const int* in_sizes, int n_in,
                              void* d_out, int out_size) {
    const float* x     = (const float*)d_in[0];
    const void*  ei    = d_in[1];
    const void*  batch = d_in[2];
    const float* W1    = (const float*)d_in[3];
    const float* b1    = (const float*)d_in[4];
    const float* W2    = (const float*)d_in[5];
    const float* b2    = (const float*)d_in[6];
    const float* Wfc   = (const float*)d_in[7];
    const float* bfc   = (const float*)d_in[8];
    float* out = (float*)d_out;

    int N = in_sizes[0] / NF;              // 100000
    int E = in_sizes[1] / 2;               // 1600000
    if (N > NN) N = NN;
    if (E > NE) E = NE;

    int nScan  = (N + 511) / 512;
    int bEdge  = (E + 255) / 256;          // 6250
    int bNode  = (N + 255) / 256;
    int bWarp  = (N + 7) / 8;              // agg: warp-per-node, 8 warps/block
    int nTiles = (N + 127) / 128;          // 782

    initdet_v17<<<bNode, 256>>>((const int*)ei, N);                    // 0
    count_v17<<<bEdge, 256>>>(ei, E, N);                               // 1
    scanf_v17<<<nScan, 512>>>(N);                                      // 2
    // gemm1 (needs dinv) overlapped with CSR fill (needs rp/pos):
    gemm_fill_v17<<<nTiles + bEdge, 256>>>(x, 1, W1, ei, E, N, nTiles);// 3  <-- profiled
    agg_v17<<<bWarp, 256>>>(b1, N);                                    // 4

    gemm_fill_v17<<<nTiles, 256>>>(x, 0, W2, ei, E, N, nTiles);        // 5 (gemm only)
    agg_v17<<<bWarp, 256>>>(b2, N);                                    // 6

    pool_v17<<<(N + PNODES - 1) / PNODES, 256>>>(batch, N);            // 7
    head_v17<<<1, 256>>>(Wfc, bfc, out);                               // 8
}